// round 11
// baseline (speedup 1.0000x reference)
#include <cuda_runtime.h>
#include <cstdint>

// LSTM_58514634440709: B=8, L=32768, H=96, 2 layers + head.
// 8 clusters x 3 CTAs. R4: quarter-split dot decomposition.
// Thread (w, q, sub): rows {g*96 + 8w+sub, g=0..3} over cols [24q,24q+24).
// 6 LDS.128 per step (vs 24), bfly-reduce over quarters, redundant c-update
// on all 4 q-lanes (no divergence). Prewait of next group's full-barrier by
// one thread; group-end BAR publishes. i/f/o weight rows pre-scaled by 0.5.

#define H 96
#define G 384
#define BATCH 8
#define NSLOT 4

struct __align__(16) Smem {
    unsigned long long fullA[NSLOT];
    unsigned long long emptyA[NSLOT];
    unsigned long long fullB[NSLOT];
    unsigned long long emptyB[NSLOT];
    union {
        float ustage[NSLOT][4][G];     // CTA1 staging
        float slotB[NSLOT][4][G];      // CTA2 inbox
    };
    union {
        float hgrp[NSLOT][4][H];       // CTA0 staging
        float slotA[NSLOT][4][H];      // CTA1 inbox
    };
    float hcur[2][H];
    float wpart[2][16];
    float xstage[2][4];
};

__device__ __forceinline__ uint32_t saddr(const void* p) {
    return (uint32_t)__cvta_generic_to_shared(p);
}
__device__ __forceinline__ uint32_t mapa_rank(uint32_t a, uint32_t r) {
    uint32_t d;
    asm("mapa.shared::cluster.u32 %0, %1, %2;" : "=r"(d) : "r"(a), "r"(r));
    return d;
}
__device__ __forceinline__ void mbar_init(uint32_t a, uint32_t cnt) {
    asm volatile("mbarrier.init.shared.b64 [%0], %1;" :: "r"(a), "r"(cnt) : "memory");
}
__device__ __forceinline__ void expect_tx(uint32_t a, uint32_t bytes) {
    asm volatile("mbarrier.arrive.expect_tx.shared.b64 _, [%0], %1;"
                 :: "r"(a), "r"(bytes) : "memory");
}
__device__ __forceinline__ void arrive_remote(uint32_t a) {
    asm volatile("mbarrier.arrive.release.cluster.shared::cluster.b64 _, [%0];"
                 :: "r"(a) : "memory");
}
__device__ __forceinline__ void fence_proxy() {
    asm volatile("fence.proxy.async.shared::cta;" ::: "memory");
}
__device__ __forceinline__ void bulk_s2s(uint32_t dst, uint32_t src,
                                         uint32_t bytes, uint32_t mbar) {
    asm volatile(
        "cp.async.bulk.shared::cluster.shared::cta.mbarrier::complete_tx::bytes "
        "[%0], [%1], %2, [%3];"
        :: "r"(dst), "r"(src), "r"(bytes), "r"(mbar) : "memory");
}
__device__ __forceinline__ void wait_par(uint32_t a, uint32_t par) {
    asm volatile(
        "{\n\t"
        ".reg .pred P;\n\t"
        "WLOOP_%=:\n\t"
        "mbarrier.try_wait.parity.acquire.cluster.shared::cta.b64 P, [%0], %1, 0x989680;\n\t"
        "@P bra WDONE_%=;\n\t"
        "bra WLOOP_%=;\n\t"
        "WDONE_%=:\n\t"
        "}" :: "r"(a), "r"(par) : "memory");
}

#define FMA2(acc, w, h) asm("fma.rn.f32x2 %0, %1, %2, %0;" : "+l"(acc) : "l"(w), "l"(h))

__device__ __forceinline__ float tanhap(float x) {
    float y;
    asm("tanh.approx.f32 %0, %1;" : "=f"(y) : "f"(x));
    return y;
}
__device__ __forceinline__ unsigned long long packf2(float lo, float hi) {
    unsigned long long r;
    asm("mov.b64 %0, {%1, %2};" : "=l"(r) : "f"(lo), "f"(hi));
    return r;
}
__device__ __forceinline__ float lohi_add(unsigned long long a) {
    float lo, hi;
    asm("mov.b64 {%0, %1}, %2;" : "=f"(lo), "=f"(hi) : "l"(a));
    return lo + hi;
}

// 4 partial dots (rows g=0..3) over this thread's 24-col quarter, then
// butterfly-reduce across the 4 quarters. Result: full z-dot in ALL lanes.
__device__ __forceinline__ void dot4q(const unsigned long long (&w2)[4][12],
                                      const float* hsrc, int q, float r[4]) {
    const ulonglong2* hp = (const ulonglong2*)(hsrc + 24 * q);
    ulonglong2 hv0 = hp[0], hv1 = hp[1], hv2 = hp[2],
               hv3 = hp[3], hv4 = hp[4], hv5 = hp[5];
    unsigned long long hh[12] = {hv0.x, hv0.y, hv1.x, hv1.y, hv2.x, hv2.y,
                                 hv3.x, hv3.y, hv4.x, hv4.y, hv5.x, hv5.y};
#pragma unroll
    for (int g = 0; g < 4; g++) {
        unsigned long long acc = 0ull;
#pragma unroll
        for (int m = 0; m < 12; m++) FMA2(acc, w2[g][m], hh[m]);
        r[g] = lohi_add(acc);
    }
#pragma unroll
    for (int g = 0; g < 4; g++) r[g] += __shfl_xor_sync(0xffffffffu, r[g], 8);
#pragma unroll
    for (int g = 0; g < 4; g++) r[g] += __shfl_xor_sync(0xffffffffu, r[g], 16);
}

// gates -> new (c, h). z0=i, z1=f (pre-halved), z2=g, z3=o (pre-halved).
__device__ __forceinline__ float lstm_act(const float z[4], float& c) {
    float ig = __fmaf_rn(0.5f, tanhap(z[0]), 0.5f);
    float fg = __fmaf_rn(0.5f, tanhap(z[1]), 0.5f);
    float gg = tanhap(z[2]);
    float og = __fmaf_rn(0.5f, tanhap(z[3]), 0.5f);
    c = __fmaf_rn(fg, c, ig * gg);
    return og * tanhap(c);
}

__global__ void __cluster_dims__(3, 1, 1) __launch_bounds__(384, 1)
lstm_pipe_kernel(const float* __restrict__ x,
                 const float* __restrict__ Wih0,
                 const float* __restrict__ Whh0,
                 const float* __restrict__ b0,
                 const float* __restrict__ Wih1,
                 const float* __restrict__ Whh1,
                 const float* __restrict__ b1,
                 const float* __restrict__ h0in,
                 const float* __restrict__ c0in,
                 const float* __restrict__ headw,
                 const float* __restrict__ headb,
                 float* __restrict__ out,
                 int L)
{
    __shared__ Smem sm;
    const int tid = threadIdx.x;
    uint32_t rank;
    asm("mov.u32 %0, %%cluster_ctarank;" : "=r"(rank));
    const int batch = blockIdx.x / 3;
    const int lane = tid & 31;
    const int w    = tid >> 5;
    const int sub  = lane & 7;
    const int q    = lane >> 3;
    const int hidx = w * 8 + sub;

    if (tid == 0) {
#pragma unroll
        for (int s = 0; s < NSLOT; s++) {
            mbar_init(saddr(&sm.fullA[s]), 1);
            mbar_init(saddr(&sm.emptyA[s]), 1);
            mbar_init(saddr(&sm.fullB[s]), 1);
            mbar_init(saddr(&sm.emptyB[s]), 1);
        }
    }

    // Weight rows for this thread: g*96 + hidx, cols [24q, 24q+24).
    // i/f/o rows (g != 2) pre-scaled by 0.5 for the sigmoid identity.
    const float* Wsrc = (rank == 0) ? Whh0 : (rank == 1) ? Wih1 : Whh1;
    unsigned long long w2[4][12];
    float bias[4], wx[4];
#pragma unroll
    for (int g = 0; g < 4; g++) {
        int row = g * H + hidx;
        float sc = (g == 2) ? 1.f : 0.5f;
        const float4* w4 = (const float4*)(Wsrc + row * H + 24 * q);
#pragma unroll
        for (int m = 0; m < 6; m++) {
            float4 v = w4[m];
            w2[g][2 * m]     = packf2(sc * v.x, sc * v.y);
            w2[g][2 * m + 1] = packf2(sc * v.z, sc * v.w);
        }
        bias[g] = (rank == 0) ? sc * b0[row] : (rank == 1) ? sc * b1[row] : 0.f;
        wx[g]   = (rank == 0) ? sc * Wih0[row] : 0.f;
    }
    float c = 0.f, hw = 0.f;
    if (rank == 0) c = c0in[hidx];
    if (rank == 2) { c = c0in[H + hidx]; hw = headw[hidx]; }
    float hb = (rank == 2) ? headb[0] : 0.f;
    if (tid < H) {
        if (rank == 0) sm.hcur[0][tid] = h0in[tid];
        if (rank == 2) sm.hcur[0][tid] = h0in[H + tid];
    }
    if (rank == 0 && tid == 25) {
        float4 x0 = __ldg((const float4*)(x + batch * L));
        *(float4*)sm.xstage[0] = x0;
    }
    __syncthreads();
    asm volatile("barrier.cluster.arrive.aligned;" ::: "memory");
    asm volatile("barrier.cluster.wait.aligned;" ::: "memory");

    const int ng = L >> 2;

    if (rank == 0) {
        const float* xb = x + batch * L;
        uint32_t rSlotA = mapa_rank(saddr(&sm.slotA[0][0][0]), 1);
        uint32_t rFullA = mapa_rank(saddr(&sm.fullA[0]), 1);
        uint32_t eA     = saddr(&sm.emptyA[0]);
        for (int gi = 0; gi < ng; gi++) {
            int s = gi & (NSLOT - 1);
#define L0STEP(j, rb, wb, EXTRAS)                                              \
            {                                                                  \
                float xc = sm.xstage[gi & 1][j];                               \
                float bx[4];                                                   \
                _Pragma("unroll")                                              \
                for (int g = 0; g < 4; g++)                                    \
                    bx[g] = __fmaf_rn(xc, wx[g], bias[g]);                     \
                float r[4];                                                    \
                dot4q(w2, sm.hcur[rb], q, r);                                  \
                _Pragma("unroll")                                              \
                for (int g = 0; g < 4; g++) r[g] += bx[g];                     \
                float hv = lstm_act(r, c);                                     \
                if (q == 0) sm.hcur[wb][hidx]   = hv;                          \
                if (q == 1) sm.hgrp[s][j][hidx] = hv;                          \
                EXTRAS                                                         \
                __syncthreads();                                               \
            }
            L0STEP(0, 0, 1,
                if (tid == 25 && gi + 1 < ng) {
                    float4 nx = __ldg((const float4*)(xb + 4 * (gi + 1)));
                    *(float4*)sm.xstage[(gi + 1) & 1] = nx;
                }
                if (tid == 24 && gi > 0) {
                    int ps = (gi - 1) & (NSLOT - 1);
                    uint32_t pfp = (uint32_t)((gi - 1) >> 2) & 1u;
                    fence_proxy();
                    wait_par(eA + 8u * ps, 1u ^ pfp);
                    bulk_s2s(rSlotA + 1536u * ps, saddr(&sm.hgrp[ps][0][0]),
                             1536u, rFullA + 8u * ps);
                }
            )
            L0STEP(1, 1, 0, )
            L0STEP(2, 0, 1, )
            L0STEP(3, 1, 0, )
#undef L0STEP
        }
        if (tid == 24) {
            int ps = (ng - 1) & (NSLOT - 1);
            uint32_t pfp = (uint32_t)((ng - 1) >> 2) & 1u;
            fence_proxy();
            wait_par(eA + 8u * ps, 1u ^ pfp);
            bulk_s2s(rSlotA + 1536u * ps, saddr(&sm.hgrp[ps][0][0]),
                     1536u, rFullA + 8u * ps);
        }
    } else if (rank == 1) {
        uint32_t fA      = saddr(&sm.fullA[0]);
        uint32_t eB      = saddr(&sm.emptyB[0]);
        uint32_t rEmptyA = mapa_rank(saddr(&sm.emptyA[0]), 0);
        uint32_t rSlotB  = mapa_rank(saddr(&sm.slotB[0][0][0]), 2);
        uint32_t rFullB  = mapa_rank(saddr(&sm.fullB[0]), 2);
        if (tid == 64) {            // prewait group 0
            expect_tx(fA, 1536u);
            wait_par(fA, 0u);
        }
        __syncthreads();
        for (int gi = 0; gi < ng; gi++) {
            int s = gi & (NSLOT - 1);
            if (gi > 0) {
                int ps = (gi - 1) & (NSLOT - 1);
                uint32_t pfp = (uint32_t)((gi - 1) >> 2) & 1u;
                if (tid == 1) arrive_remote(rEmptyA + 8u * ps);
                if (tid == 32) {
                    fence_proxy();
                    wait_par(eB + 8u * ps, 1u ^ pfp);
                    bulk_s2s(rSlotB + 6144u * ps, saddr(&sm.ustage[ps][0][0]),
                             6144u, rFullB + 8u * ps);
                }
            }
#pragma unroll
            for (int j = 0; j < 4; j++) {
                float r[4];
                dot4q(w2, sm.slotA[s][j], q, r);
                // lane writes its own gate (q) for its h-index
                sm.ustage[s][j][q * H + hidx] = r[q] + bias[q];
            }
            if (tid == 64 && gi + 1 < ng) {   // prewait next group
                int ns = (gi + 1) & (NSLOT - 1);
                expect_tx(fA + 8u * ns, 1536u);
                wait_par(fA + 8u * ns, (uint32_t)((gi + 1) >> 2) & 1u);
            }
            __syncthreads();
        }
        if (tid == 32) {
            int ps = (ng - 1) & (NSLOT - 1);
            uint32_t pfp = (uint32_t)((ng - 1) >> 2) & 1u;
            fence_proxy();
            wait_par(eB + 8u * ps, 1u ^ pfp);
            bulk_s2s(rSlotB + 6144u * ps, saddr(&sm.ustage[ps][0][0]),
                     6144u, rFullB + 8u * ps);
        }
    } else {
        uint32_t fB      = saddr(&sm.fullB[0]);
        uint32_t rEmptyB = mapa_rank(saddr(&sm.emptyB[0]), 1);
        float* yb = out + batch * L;
        if (tid == 64) {            // prewait group 0
            expect_tx(fB, 6144u);
            wait_par(fB, 0u);
        }
        __syncthreads();
        for (int gi = 0; gi < ng; gi++) {
            int s = gi & (NSLOT - 1);
            if (tid == 1 && gi > 0)
                arrive_remote(rEmptyB + 8u * ((gi - 1) & (NSLOT - 1)));
#define L2STEP(j, rb, wb, EXTRAS)                                              \
            {                                                                  \
                int t = 4 * gi + j;                                            \
                /* head partial for h(t-1), parallel with the dot */           \
                float hp = sm.hcur[rb][hidx] * hw;                             \
                float r[4];                                                    \
                dot4q(w2, sm.hcur[rb], q, r);                                  \
                float z[4];                                                    \
                _Pragma("unroll")                                              \
                for (int g = 0; g < 4; g++)                                    \
                    z[g] = r[g] + sm.slotB[s][j][g * H + hidx];                \
                float hv = lstm_act(z, c);                                     \
                if (q == 0) sm.hcur[wb][hidx] = hv;                            \
                hp += __shfl_xor_sync(0xffffffffu, hp, 1);                     \
                hp += __shfl_xor_sync(0xffffffffu, hp, 2);                     \
                hp += __shfl_xor_sync(0xffffffffu, hp, 4);                     \
                if (lane == 8 && t >= 1) sm.wpart[(t - 1) & 1][w] = hp;        \
                if (tid == 26 && t >= 2) {                                     \
                    const float4* qq = (const float4*)sm.wpart[t & 1];         \
                    float4 qa = qq[0], qb = qq[1], qc = qq[2];                 \
                    yb[t - 2] = hb + qa.x + qa.y + qa.z + qa.w                 \
                                   + qb.x + qb.y + qb.z + qb.w                 \
                                   + qc.x + qc.y + qc.z + qc.w;                \
                }                                                              \
                EXTRAS                                                         \
                __syncthreads();                                               \
            }
            L2STEP(0, 0, 1, )
            L2STEP(1, 1, 0, )
            L2STEP(2, 0, 1,
                if (tid == 64 && gi + 1 < ng) {
                    int ns = (gi + 1) & (NSLOT - 1);
                    expect_tx(fB + 8u * ns, 6144u);
                    wait_par(fB + 8u * ns, (uint32_t)((gi + 1) >> 2) & 1u);
                }
            )
            L2STEP(3, 1, 0, )
#undef L2STEP
        }
        // drain: partial for h(L-1) (in hcur[0]), then y(L-2), y(L-1)
        {
            float hp = sm.hcur[0][hidx] * hw;
            hp += __shfl_xor_sync(0xffffffffu, hp, 1);
            hp += __shfl_xor_sync(0xffffffffu, hp, 2);
            hp += __shfl_xor_sync(0xffffffffu, hp, 4);
            if (lane == 8) sm.wpart[1][w] = hp;
        }
        if (tid == 26) {
            const float4* qq = (const float4*)sm.wpart[0];
            float4 qa = qq[0], qb = qq[1], qc = qq[2];
            yb[L - 2] = hb + qa.x + qa.y + qa.z + qa.w
                           + qb.x + qb.y + qb.z + qb.w
                           + qc.x + qc.y + qc.z + qc.w;
        }
        __syncthreads();
        if (tid == 26) {
            const float4* qq = (const float4*)sm.wpart[1];
            float4 qa = qq[0], qb = qq[1], qc = qq[2];
            yb[L - 1] = hb + qa.x + qa.y + qa.z + qa.w
                           + qb.x + qb.y + qb.z + qb.w
                           + qc.x + qc.y + qc.z + qc.w;
        }
    }

    asm volatile("barrier.cluster.arrive.aligned;" ::: "memory");
    asm volatile("barrier.cluster.wait.aligned;" ::: "memory");
}

extern "C" void kernel_launch(void* const* d_in, const int* in_sizes, int n_in,
                              void* d_out, int out_size) {
    const float* x     = (const float*)d_in[0];
    const float* Wih0  = (const float*)d_in[1];
    const float* Whh0  = (const float*)d_in[2];
    const float* b0    = (const float*)d_in[3];
    const float* Wih1  = (const float*)d_in[4];
    const float* Whh1  = (const float*)d_in[5];
    const float* b1    = (const float*)d_in[6];
    const float* h0in  = (const float*)d_in[7];
    const float* c0in  = (const float*)d_in[8];
    const float* headw = (const float*)d_in[9];
    const float* headb = (const float*)d_in[10];
    float* out = (float*)d_out;
    int L = in_sizes[0] / BATCH;

    lstm_pipe_kernel<<<BATCH * 3, 384>>>(x, Wih0, Whh0, b0, Wih1, Whh1, b1,
                                         h0in, c0in, headw, headb, out, L);
}